// round 10
// baseline (speedup 1.0000x reference)
#include <cuda_runtime.h>
#include <cuda_bf16.h>

// Problem constants
#define S_   8192
#define LC_  16
#define D_   256
#define CV_  128
#define DC_  64
#define HC_  128
#define H_   256
#define T_   17
// derived
#define G4C  (4*HC_)        // 512 char gates
#define G4W  (4*H_)         // 1024 word gates
#define KW   (HC_ + H_)     // 384 recurrent-x length for word LSTM

typedef unsigned long long ull;

// ---------------- device scratch (no allocation allowed) ----------------
__device__ __align__(16) float g_xg_tab[CV_ * G4C];        // 256 KB: per-char input gates
__device__ __align__(16) float g_wg[S_ * G4W];             // 32 MB : word-emb gate contributions (+b_w)
__device__ __align__(16) float g_WcatT[(KW/4) * G4W * 4];  // 1.5 MB: [k4][1024][4] k-major (hc|hw part)
__device__ __align__(16) float g_WweT[(D_/4) * G4W * 4];   // 1 MB  : [k4][1024][4] k-major (we part)

// ---------------- helpers ----------------
__device__ __forceinline__ void fma2(ull &acc, ull a, ull b) {
    asm("fma.rn.f32x2 %0, %1, %2, %0;" : "+l"(acc) : "l"(a), "l"(b));
}
__device__ __forceinline__ float redu(ull a) {
    return __uint_as_float((unsigned)(a & 0xffffffffull)) +
           __uint_as_float((unsigned)(a >> 32));
}
__device__ __forceinline__ float sigf(float x) {
    return __fdividef(1.0f, 1.0f + __expf(-x));
}
__device__ __forceinline__ float tanh_(float x) {
    float e = __expf(-2.0f * fabsf(x));
    float r = __fdividef(1.0f - e, 1.0f + e);
    return copysignf(r, x);
}

// ---------------- K0: per-char gate table ----------------
__global__ void xg_kernel(const float* __restrict__ Wih_c,
                          const float* __restrict__ char_emb,
                          const float* __restrict__ b_c) {
    __shared__ float ce[DC_];
    const int c = blockIdx.x, t = threadIdx.x;   // 128 blocks x 512 threads
    if (t < DC_) ce[t] = char_emb[c * DC_ + t];
    __syncthreads();
    float acc = b_c[t];
#pragma unroll
    for (int d = 0; d < DC_; ++d) acc += Wih_c[t * DC_ + d] * ce[d];
    g_xg_tab[c * G4C + t] = acc;
}

// ---------------- Kp: transpose word weights to k-major ----------------
__global__ void prep_kernel(const float* __restrict__ Wih_w,
                            const float* __restrict__ Whh_w) {
    int idx = blockIdx.x * blockDim.x + threadIdx.x;
    if (idx < (KW/4) * G4W * 4) {     // 393216
        int j  = idx & 3;
        int g  = (idx >> 2) & 1023;
        int k4 = idx >> 12;
        int k  = k4 * 4 + j;          // 0..383
        g_WcatT[idx] = (k < HC_) ? Wih_w[g * (D_ + HC_) + D_ + k]
                                 : Whh_w[g * H_ + (k - HC_)];
    }
    if (idx < (D_/4) * G4W * 4) {     // 262144
        int j  = idx & 3;
        int g  = (idx >> 2) & 1023;
        int k4 = idx >> 12;
        int k  = k4 * 4 + j;          // 0..255
        g_WweT[idx] = Wih_w[g * (D_ + HC_) + k];
    }
}

// ---------------- K1: wg[s] = we_s @ Wih_w[:, :D].T + b_w (8 words/block) ----------------
__global__ __launch_bounds__(256) void wg_kernel(const int* __restrict__ sentence,
                                                 const float* __restrict__ word_emb,
                                                 const float* __restrict__ b_w) {
    __shared__ float sh_we[8 * D_];
    __shared__ int   sh_s[8];
    const int t = threadIdx.x;                 // 256
    const int s0 = blockIdx.x * 8;             // 1024 blocks
    if (t < 8) sh_s[t] = sentence[s0 + t];
    __syncthreads();
    for (int i = t; i < 8 * D_; i += 256) {
        int w = i >> 8, d = i & (D_ - 1);
        sh_we[i] = word_emb[(long long)sh_s[w] * D_ + d];
    }
    __syncthreads();

    float acc[4][8];
#pragma unroll
    for (int q = 0; q < 4; ++q)
#pragma unroll
        for (int w = 0; w < 8; ++w) acc[q][w] = 0.f;

    const float4* WT  = (const float4*)g_WweT;   // [k4][1024]
    const float4* we4 = (const float4*)sh_we;    // [w][64]
    for (int k4 = 0; k4 < D_/4; ++k4) {
        float4 wv[4];
#pragma unroll
        for (int q = 0; q < 4; ++q) wv[q] = WT[k4 * G4W + q * 256 + t];
#pragma unroll
        for (int w = 0; w < 8; ++w) {
            float4 xv = we4[w * (D_/4) + k4];
#pragma unroll
            for (int q = 0; q < 4; ++q)
                acc[q][w] += wv[q].x * xv.x + wv[q].y * xv.y +
                             wv[q].z * xv.z + wv[q].w * xv.w;
        }
    }
#pragma unroll
    for (int q = 0; q < 4; ++q) {
        float bb = b_w[q * 256 + t];
#pragma unroll
        for (int w = 0; w < 8; ++w)
            g_wg[(s0 + w) * G4W + q * 256 + t] = acc[q][w] + bb;
    }
}

// ---------------- K2: the sequential scan (single CTA) ----------------
// smem layout (dynamic):
//   [0      , 65536)  sh_wc : ull[16][512]  (Whh_c k=96..127, pair-major)
//   [65536  , 67072)  sh_x  : float[384]    (hc | hw)
//   [67072  , 71168)  sh_g  : float[1024]
//   [71168  , 88576)  sh_wout: float[17*256]
//   [88576  , 88704)  sh_bout: float[17]
//   [88704  , 88832)  sh_ch : int[17] (16 chars + len)
#define SMEM_BYTES 90112

__global__ __launch_bounds__(512, 1) void seq_kernel(
    const int*   __restrict__ word_chars,
    const int*   __restrict__ char_lens,
    const float* __restrict__ Whh_c,
    const float* __restrict__ Wout,
    const float* __restrict__ bout,
    float*       __restrict__ out) {

    extern __shared__ unsigned char smraw[];
    ull*   sh_wc   = (ull*)smraw;
    float* sh_x    = (float*)(smraw + 65536);
    float* sh_g    = (float*)(smraw + 67072);
    float* sh_wout = (float*)(smraw + 71168);
    float* sh_bout = (float*)(smraw + 88576);
    int*   sh_ch   = (int*)(smraw + 88704);

    const int t = threadIdx.x;    // 512

    // Register-resident Whh_c row t, k = 0..95 (48 packed pairs);
    // k = 96..127 goes to smem, pair-major so loads are conflict-free.
    ull wr[48];
    {
        const ull* wrow = (const ull*)(Whh_c + t * HC_);   // 512B-aligned row
#pragma unroll
        for (int i = 0; i < 48; ++i) wr[i] = wrow[i];
#pragma unroll
        for (int i = 0; i < 16; ++i) sh_wc[i * 512 + t] = wrow[48 + i];
    }
    for (int i = t; i < T_ * H_; i += 512) sh_wout[i] = Wout[i];
    if (t < T_) sh_bout[t] = bout[t];
    for (int i = t; i < KW; i += 512) sh_x[i] = 0.f;
    float ccr = 0.f;   // cell state, char LSTM  (owned by t<128)
    float cwr = 0.f;   // cell state, word LSTM  (owned by t<256)
    __syncthreads();

    const ulonglong2* hp = (const ulonglong2*)sh_x;      // 96 x 16B over [hc|hw]
    const ulonglong2* Wp = (const ulonglong2*)g_WcatT;   // [k4][1024]

    for (int s = 0; s < S_; ++s) {
        if (t < LC_)  sh_ch[t]  = word_chars[s * LC_ + t];
        if (t == LC_) sh_ch[LC_] = char_lens[s];
        __syncthreads();
        const int len = sh_ch[LC_];

        // -------- char LSTM steps (skip frozen t >= len steps) --------
        for (int ct = 0; ct < len; ++ct) {
            const int ch = sh_ch[ct];
            float xg = g_xg_tab[ch * G4C + t];   // L2-hot, hoisted load
            ull a0 = 0, a1 = 0;
#pragma unroll
            for (int i = 0; i < 24; ++i) {       // k = 0..95 from registers
                ulonglong2 hv = hp[i];
                fma2(a0, wr[2 * i],     hv.x);
                fma2(a1, wr[2 * i + 1], hv.y);
            }
#pragma unroll
            for (int i = 0; i < 8; ++i) {        // k = 96..127 from smem
                ulonglong2 hv = hp[24 + i];
                fma2(a0, sh_wc[(2 * i) * 512 + t],     hv.x);
                fma2(a1, sh_wc[(2 * i + 1) * 512 + t], hv.y);
            }
            sh_g[t] = xg + redu(a0) + redu(a1);
            __syncthreads();
            if (t < HC_) {
                float gi = sigf(sh_g[t]);
                float gf = sigf(sh_g[HC_ + t]);
                float gg = tanh_(sh_g[2 * HC_ + t]);
                float go = sigf(sh_g[3 * HC_ + t]);
                ccr = gf * ccr + gi * gg;
                sh_x[t] = go * tanh_(ccr);
            }
            __syncthreads();
        }

        // -------- word LSTM step --------
        float wgl0 = g_wg[s * G4W + t];          // we-part + bias, precomputed
        float wgl1 = g_wg[s * G4W + 512 + t];
        ull b0 = 0, b1 = 0, b2 = 0, b3 = 0;
#pragma unroll 4
        for (int i = 0; i < KW/4; ++i) {         // 96 iterations over [hc|hw]
            ulonglong2 xv = hp[i];
            ulonglong2 wa = Wp[i * G4W + t];
            ulonglong2 wb = Wp[i * G4W + 512 + t];
            fma2(b0, wa.x, xv.x);  fma2(b1, wa.y, xv.y);
            fma2(b2, wb.x, xv.x);  fma2(b3, wb.y, xv.y);
        }
        sh_g[t]       = wgl0 + redu(b0) + redu(b1);
        sh_g[512 + t] = wgl1 + redu(b2) + redu(b3);
        __syncthreads();
        if (t < H_) {
            float gi = sigf(sh_g[t]);
            float gf = sigf(sh_g[H_ + t]);
            float gg = tanh_(sh_g[2 * H_ + t]);
            float go = sigf(sh_g[3 * H_ + t]);
            cwr = gf * cwr + gi * gg;
            sh_x[HC_ + t] = go * tanh_(cwr);
        }
        __syncthreads();

        // -------- logits: 17 outputs x 16 threads each --------
        {
            int o = t >> 4; if (o > 16) o = 16;   // clamp so all lanes stay converged
            int l16 = t & 15;
            const float4* wo4 = (const float4*)sh_wout;        // [17][64]
            const float4* xw4 = (const float4*)(sh_x + HC_);   // hw as [64] float4
            float acc = 0.f;
#pragma unroll
            for (int j = 0; j < 4; ++j) {
                float4 w  = wo4[o * (H_/4) + l16 * 4 + j];
                float4 xv = xw4[l16 * 4 + j];
                acc += w.x * xv.x + w.y * xv.y + w.z * xv.z + w.w * xv.w;
            }
            acc += __shfl_xor_sync(0xffffffffu, acc, 8);
            acc += __shfl_xor_sync(0xffffffffu, acc, 4);
            acc += __shfl_xor_sync(0xffffffffu, acc, 2);
            acc += __shfl_xor_sync(0xffffffffu, acc, 1);
            if (t < T_ * 16 && l16 == 0) out[s * T_ + o] = acc + sh_bout[o];
        }
        __syncthreads();
    }
}

// ---------------- launch ----------------
extern "C" void kernel_launch(void* const* d_in, const int* in_sizes, int n_in,
                              void* d_out, int out_size) {
    const int*   sentence   = (const int*)  d_in[0];
    const int*   word_chars = (const int*)  d_in[1];
    const int*   char_lens  = (const int*)  d_in[2];
    const float* word_emb   = (const float*)d_in[3];
    const float* char_emb   = (const float*)d_in[4];
    const float* Wih_c      = (const float*)d_in[5];
    const float* Whh_c      = (const float*)d_in[6];
    const float* b_c        = (const float*)d_in[7];
    const float* Wih_w      = (const float*)d_in[8];
    const float* Whh_w      = (const float*)d_in[9];
    const float* b_w        = (const float*)d_in[10];
    const float* Wout       = (const float*)d_in[11];
    const float* bout       = (const float*)d_in[12];
    float* out = (float*)d_out;

    (void)in_sizes; (void)n_in; (void)out_size;

    prep_kernel<<<1536, 256>>>(Wih_w, Whh_w);
    xg_kernel<<<CV_, G4C>>>(Wih_c, char_emb, b_c);
    wg_kernel<<<S_ / 8, 256>>>(sentence, word_emb, b_w);

    cudaFuncSetAttribute(seq_kernel,
                         cudaFuncAttributeMaxDynamicSharedMemorySize, SMEM_BYTES);
    seq_kernel<<<1, 512, SMEM_BYTES>>>(word_chars, char_lens, Whh_c, Wout, bout, out);
}